// round 14
// baseline (speedup 1.0000x reference)
#include <cuda_runtime.h>
#include <cuda_fp16.h>
#include <cstdint>

// CachedMPS on GB300 — fp16 m16n8k16 split HMMA chain, paired steps.
// R14: 32 rows/warp (two m16 row-groups). B-fragments are IDENTICAL for both
// groups -> each LDS.128 feeds 6 MMAs (was 3): chip LDS traffic halves while
// per-SMSP MMA work is unchanged. R13 post-hoc scalars kept (A split once,
// unscaled; fold acc = sum sc[ci]*P[ci] afterwards). R12 scale engineering
// kept (W x64 in prep; renormalize to 256 every 2 pairs; final eps-free
// unit-normalize). Split exact: hi = v & 0xFFFFE000, lo = v - hi.

#define DEV_INLINE __device__ __forceinline__

static constexpr int D     = 32;
static constexpr int L     = 256;
static constexpr int NPAIR = 127;
static constexpr int C     = 10;
static constexpr int TPB   = 128;             // 4 warps x 32 rows = 128 rows/CTA
static constexpr int ROWS_PER_CTA = 128;
static constexpr float HALF_PI = 1.57079632679489662f;
static constexpr float W_SCALE  = 64.0f;
static constexpr float NORM_TGT = 256.0f;
static constexpr unsigned H_MASK = 0xFFFFE000u;

// composite-W scratch: [NPAIR][4096] u32 (f16x2-packed hi/lo, frag-native)
__device__ unsigned g_Bt[(size_t)NPAIR * 4096];

DEV_INLINE unsigned smem_u32(const void* p) {
    unsigned r;
    asm("{ .reg .u64 t; cvta.to.shared.u64 t, %1; cvt.u32.u64 %0, t; }" : "=r"(r) : "l"(p));
    return r;
}
DEV_INLINE void cp16(unsigned dst, const void* src) {
    asm volatile("cp.async.cg.shared.global [%0], [%1], 16;" :: "r"(dst), "l"(src));
}
DEV_INLINE void cp_commit() { asm volatile("cp.async.commit_group;"); }
DEV_INLINE void cp_wait0()  { asm volatile("cp.async.wait_group 0;" ::: "memory"); }

DEV_INLINE unsigned packh2(float lo, float hi) {
    unsigned r; asm("cvt.rn.f16x2.f32 %0, %1, %2;" : "=r"(r) : "f"(hi), "f"(lo));
    return r;
}

DEV_INLINE void mma16(float* c, const unsigned* a, unsigned b0, unsigned b1) {
    asm("mma.sync.aligned.m16n8k16.row.col.f32.f16.f16.f32 "
        "{%0,%1,%2,%3}, {%4,%5,%6,%7}, {%8,%9}, {%0,%1,%2,%3};"
        : "+f"(c[0]), "+f"(c[1]), "+f"(c[2]), "+f"(c[3])
        : "r"(a[0]), "r"(a[1]), "r"(a[2]), "r"(a[3]), "r"(b0), "r"(b1));
}

DEV_INLINE void msplit(float v, float& hf, float& lf) {
    const unsigned h = __float_as_uint(v) & H_MASK;
    hf = __uint_as_float(h);
    lf = v - hf;
}

// ---- prep: composite pair products x64 -> f16 hi/lo, B-frag-native ----
// (layout verified R10/R12/R13)
__global__ void prep_pairs(const float* __restrict__ cores_mid) {
    __shared__ float sW0[2048], sW1[2048];
    const int p = blockIdx.x;
    const float* s0 = cores_mid + (size_t)(2 * p) * 2048;
    const float* s1 = cores_mid + (size_t)(2 * p + 1) * 2048;
    for (int i = threadIdx.x; i < 2048; i += blockDim.x) { sW0[i] = s0[i]; sW1[i] = s1[i]; }
    __syncthreads();

    unsigned* dst = g_Bt + (size_t)p * 4096;
    for (int i = threadIdx.x; i < 4096; i += blockDim.x) {
        const int s = i & 3, lane = (i >> 2) & 31, tj = i >> 7;
        const int T = tj >> 2, j = tj & 3;
        const int q = lane & 3, g = lane >> 2;
        const int reg = s & 1, term = s >> 1;
        const int k0 = 16 * T + 2 * q + 8 * reg;
        const int n  = 8 * j + g;

        float v[2];
        #pragma unroll
        for (int e = 0; e < 2; e++) {
            const int k = k0 + e, ci = k >> 5, a = k & 31;
            const float* r0 = sW0 + (ci & 1) * 1024 + a * 32;
            const float* r1 = sW1 + (ci >> 1) * 1024 + n;
            float acc = 0.f;
            #pragma unroll 8
            for (int cc = 0; cc < 32; cc++) acc += r0[cc] * r1[cc * 32];
            v[e] = acc * W_SCALE;
        }
        float h0, l0, h1, l1;
        msplit(v[0], h0, l0);
        msplit(v[1], h1, l1);
        dst[i] = (term == 0) ? packh2(h0, h1) : packh2(l0, l1);
    }
}

__global__ void __launch_bounds__(TPB, 2)
mps_hmma_kernel(const float* __restrict__ x,
                const float* __restrict__ core0,
                const float* __restrict__ coreN,
                float* __restrict__ out, int B)
{
    __shared__ __align__(16) unsigned sW[2][4096];   // 2 stages x 16KB

    const int tid  = threadIdx.x;
    const int lane = tid & 31;
    const int w    = tid >> 5;
    const int q    = lane & 3;
    const int g    = lane >> 2;
    const int rowbase = blockIdx.x * ROWS_PER_CTA + w * 32;

    // 4 chain rows per lane: rr = 2*m + rs -> row = rowbase + 16m + g + 8rs
    int rows[4];
    #pragma unroll
    for (int rr = 0; rr < 4; rr++)
        rows[rr] = min(rowbase + 16 * (rr >> 1) + g + 8 * (rr & 1), B - 1);

    // prefetch pair-0 tile (16KB, 8 cp16/thread)
    {
        const unsigned* gsrc = g_Bt;
        const unsigned sb = smem_u32(&sW[0][0]);
        #pragma unroll
        for (int i = 0; i < 8; i++) {
            const int idx = tid + i * TPB;
            cp16(sb + idx * 16, gsrc + idx * 4);
        }
        cp_commit();
    }

    // ---- init acc[m] = M0 (c-frag layout per group), normalize to NORM_TGT ----
    float acc[2][16];
    #pragma unroll
    for (int m = 0; m < 2; m++)
        #pragma unroll
        for (int rs = 0; rs < 2; rs++) {
            float s0, c0;
            __sincosf(HALF_PI * __ldg(x + (size_t)rows[2 * m + rs] * L), &s0, &c0);
            #pragma unroll
            for (int j = 0; j < 4; j++)
                #pragma unroll
                for (int pp = 0; pp < 2; pp++) {
                    const int col = 8 * j + 2 * q + pp;
                    acc[m][4 * j + 2 * rs + pp] = c0 * core0[col] + s0 * core0[32 + col];
                }
        }
    #pragma unroll
    for (int m = 0; m < 2; m++)
        #pragma unroll
        for (int rs = 0; rs < 2; rs++) {
            float ss = 0.f;
            #pragma unroll
            for (int j = 0; j < 4; j++) {
                const float v0 = acc[m][4 * j + 2 * rs];
                const float v1 = acc[m][4 * j + 2 * rs + 1];
                ss += v0 * v0 + v1 * v1;
            }
            ss += __shfl_xor_sync(0xffffffffu, ss, 1);
            ss += __shfl_xor_sync(0xffffffffu, ss, 2);
            const float r = NORM_TGT * rsqrtf(ss);
            #pragma unroll
            for (int j = 0; j < 4; j++) {
                acc[m][4 * j + 2 * rs]     *= r;
                acc[m][4 * j + 2 * rs + 1] *= r;
            }
        }

    // pair-0 scalars: sc[ci][rr]
    float sc[4][4];
    #pragma unroll
    for (int rr = 0; rr < 4; rr++) {
        float s1v, c1v, s2v, c2v;
        __sincosf(HALF_PI * __ldg(x + (size_t)rows[rr] * L + 1), &s1v, &c1v);
        __sincosf(HALF_PI * __ldg(x + (size_t)rows[rr] * L + 2), &s2v, &c2v);
        sc[0][rr] = c1v * c2v;  sc[1][rr] = s1v * c2v;
        sc[2][rr] = c1v * s2v;  sc[3][rr] = s1v * s2v;
    }

    // ---- 127 composite steps ----
    for (int p = 0; p < NPAIR; p++) {
        cp_wait0();
        __syncthreads();

        if (p + 1 < NPAIR) {
            const unsigned* gsrc = g_Bt + (size_t)(p + 1) * 4096;
            const unsigned sb = smem_u32(&sW[(p + 1) & 1][0]);
            #pragma unroll
            for (int i = 0; i < 8; i++) {
                const int idx = tid + i * TPB;
                cp16(sb + idx * 16, gsrc + idx * 4);
            }
            cp_commit();
        }

        const unsigned* W = &sW[p & 1][0];

        // split A ONCE per group (unscaled); acc is dead after this
        unsigned ahi[2][2][4], alo[2][2][4];
        #pragma unroll
        for (int m = 0; m < 2; m++)
            #pragma unroll
            for (int tk = 0; tk < 2; tk++)
                #pragma unroll
                for (int i = 0; i < 4; i++) {
                    float h0, l0, h1, l1;
                    msplit(acc[m][8 * tk + 2 * i],     h0, l0);
                    msplit(acc[m][8 * tk + 2 * i + 1], h1, l1);
                    ahi[m][tk][i] = packh2(h0, h1);
                    alo[m][tk][i] = packh2(l0, l1);
                }

        #pragma unroll
        for (int ci = 0; ci < 4; ci++) {
            float P[2][16];
            #pragma unroll
            for (int m = 0; m < 2; m++)
                #pragma unroll
                for (int k = 0; k < 16; k++) P[m][k] = 0.f;

            #pragma unroll
            for (int tk = 0; tk < 2; tk++) {
                const int T = 2 * ci + tk;
                #pragma unroll
                for (int j = 0; j < 4; j++) {
                    const uint4 b = *reinterpret_cast<const uint4*>(
                        W + ((size_t)(T * 4 + j) * 32 + lane) * 4);
                    // one B load feeds BOTH row groups (6 MMAs)
                    mma16(&P[0][4 * j], ahi[0][tk], b.x, b.y);
                    mma16(&P[0][4 * j], ahi[0][tk], b.z, b.w);
                    mma16(&P[0][4 * j], alo[0][tk], b.x, b.y);
                    mma16(&P[1][4 * j], ahi[1][tk], b.x, b.y);
                    mma16(&P[1][4 * j], ahi[1][tk], b.z, b.w);
                    mma16(&P[1][4 * j], alo[1][tk], b.x, b.y);
                }
            }

            // fold: acc (+)= sc[ci][2m+rs] * P   (acc reused as nacc)
            #pragma unroll
            for (int m = 0; m < 2; m++) {
                const float s0 = sc[ci][2 * m], s1 = sc[ci][2 * m + 1];
                if (ci == 0) {
                    #pragma unroll
                    for (int j = 0; j < 4; j++) {
                        acc[m][4 * j + 0] = s0 * P[m][4 * j + 0];
                        acc[m][4 * j + 1] = s0 * P[m][4 * j + 1];
                        acc[m][4 * j + 2] = s1 * P[m][4 * j + 2];
                        acc[m][4 * j + 3] = s1 * P[m][4 * j + 3];
                    }
                } else {
                    #pragma unroll
                    for (int j = 0; j < 4; j++) {
                        acc[m][4 * j + 0] = fmaf(s0, P[m][4 * j + 0], acc[m][4 * j + 0]);
                        acc[m][4 * j + 1] = fmaf(s0, P[m][4 * j + 1], acc[m][4 * j + 1]);
                        acc[m][4 * j + 2] = fmaf(s1, P[m][4 * j + 2], acc[m][4 * j + 2]);
                        acc[m][4 * j + 3] = fmaf(s1, P[m][4 * j + 3], acc[m][4 * j + 3]);
                    }
                }
            }
        }

        // next pair's scalars (x-only; overlaps in-flight MMAs)
        if (p + 1 < NPAIR) {
            #pragma unroll
            for (int rr = 0; rr < 4; rr++) {
                float s1v, c1v, s2v, c2v;
                __sincosf(HALF_PI * __ldg(x + (size_t)rows[rr] * L + (2 * p + 3)), &s1v, &c1v);
                __sincosf(HALF_PI * __ldg(x + (size_t)rows[rr] * L + (2 * p + 4)), &s2v, &c2v);
                sc[0][rr] = c1v * c2v;  sc[1][rr] = s1v * c2v;
                sc[2][rr] = c1v * s2v;  sc[3][rr] = s1v * s2v;
            }
        }

        // rescale to NORM_TGT every 2 pairs
        if (p & 1) {
            #pragma unroll
            for (int m = 0; m < 2; m++)
                #pragma unroll
                for (int rs = 0; rs < 2; rs++) {
                    float ss = 0.f;
                    #pragma unroll
                    for (int j = 0; j < 4; j++) {
                        const float v0 = acc[m][4 * j + 2 * rs];
                        const float v1 = acc[m][4 * j + 2 * rs + 1];
                        ss += v0 * v0 + v1 * v1;
                    }
                    ss += __shfl_xor_sync(0xffffffffu, ss, 1);
                    ss += __shfl_xor_sync(0xffffffffu, ss, 2);
                    const float r = NORM_TGT * rsqrtf(ss);
                    #pragma unroll
                    for (int j = 0; j < 4; j++) {
                        acc[m][4 * j + 2 * rs]     *= r;
                        acc[m][4 * j + 2 * rs + 1] *= r;
                    }
                }
        }
    }

    // ---- readout: eps-free unit normalize + coreN contraction ----
    #pragma unroll
    for (int m = 0; m < 2; m++)
        #pragma unroll
        for (int rs = 0; rs < 2; rs++) {
            const int row = rowbase + 16 * m + g + 8 * rs;

            float ss = 0.f;
            #pragma unroll
            for (int j = 0; j < 4; j++) {
                const float v0 = acc[m][4 * j + 2 * rs];
                const float v1 = acc[m][4 * j + 2 * rs + 1];
                ss += v0 * v0 + v1 * v1;
            }
            ss += __shfl_xor_sync(0xffffffffu, ss, 1);
            ss += __shfl_xor_sync(0xffffffffu, ss, 2);
            const float inv = rsqrtf(ss);           // NO eps (R1 lesson)

            float sL, cL;
            __sincosf(HALF_PI * __ldg(x + (size_t)rows[2 * m + rs] * L + (L - 1)), &sL, &cL);

            float lg[C];
            #pragma unroll
            for (int cc = 0; cc < C; cc++) lg[cc] = 0.f;
            #pragma unroll
            for (int j = 0; j < 4; j++)
                #pragma unroll
                for (int pp = 0; pp < 2; pp++) {
                    const int col = 8 * j + 2 * q + pp;
                    const float mv = acc[m][4 * j + 2 * rs + pp];
                    #pragma unroll
                    for (int cc = 0; cc < C; cc++) {
                        const float wv = cL * coreN[col * C + cc]
                                       + sL * coreN[D * C + col * C + cc];
                        lg[cc] += mv * wv;
                    }
                }
            #pragma unroll
            for (int cc = 0; cc < C; cc++) {
                lg[cc] += __shfl_xor_sync(0xffffffffu, lg[cc], 1);
                lg[cc] += __shfl_xor_sync(0xffffffffu, lg[cc], 2);
            }
            if (q == 0 && row < B) {
                #pragma unroll
                for (int cc = 0; cc < C; cc++)
                    out[(size_t)row * C + cc] = lg[cc] * inv;
            }
        }
}

extern "C" void kernel_launch(void* const* d_in, const int* in_sizes, int n_in,
                              void* d_out, int out_size)
{
    const float* x         = (const float*)d_in[0];
    const float* core0     = (const float*)d_in[1];
    const float* cores_mid = (const float*)d_in[2];
    const float* coreN     = (const float*)d_in[3];
    float* out = (float*)d_out;

    const int B = in_sizes[0] / L;
    const int grid = (B + ROWS_PER_CTA - 1) / ROWS_PER_CTA;   // 256 for B=32768

    prep_pairs<<<NPAIR, 256>>>(cores_mid);
    mps_hmma_kernel<<<grid, TPB>>>(x, core0, coreN, out, B);
}

// round 15
// speedup vs baseline: 1.0262x; 1.0262x over previous
#include <cuda_runtime.h>
#include <cuda_fp16.h>
#include <cstdint>

// CachedMPS on GB300 — fp16 m16n8k16 split HMMA chain, paired steps.
// R15 = R13 with a restructured pipeline: barrier right after the MMA block
// (tails no longer serialize across warps), cp.async issued at loop top with
// wait_group(1) (never blocks on the just-issued stage). Arithmetic identical
// to R13: A split once unscaled (hi = v & 0xFFFFE000, lo = v - hi, exact),
// P[ci] = M x W[ci], post-hoc fold acc = sum sc[ci]*P[ci]; W x64 in prep;
// renormalize to 256 every 2 pairs; final eps-free unit-normalize.

#define DEV_INLINE __device__ __forceinline__

static constexpr int D     = 32;
static constexpr int L     = 256;
static constexpr int NPAIR = 127;
static constexpr int C     = 10;
static constexpr int TPB   = 128;             // 4 warps x 16 rows = 64 rows/CTA
static constexpr int ROWS_PER_CTA = 64;
static constexpr float HALF_PI = 1.57079632679489662f;
static constexpr float W_SCALE  = 64.0f;
static constexpr float NORM_TGT = 256.0f;
static constexpr unsigned H_MASK = 0xFFFFE000u;

// composite-W scratch: [NPAIR][4096] u32 (f16x2-packed hi/lo, frag-native)
__device__ unsigned g_Bt[(size_t)NPAIR * 4096];

DEV_INLINE unsigned smem_u32(const void* p) {
    unsigned r;
    asm("{ .reg .u64 t; cvta.to.shared.u64 t, %1; cvt.u32.u64 %0, t; }" : "=r"(r) : "l"(p));
    return r;
}
DEV_INLINE void cp16(unsigned dst, const void* src) {
    asm volatile("cp.async.cg.shared.global [%0], [%1], 16;" :: "r"(dst), "l"(src));
}
DEV_INLINE void cp_commit() { asm volatile("cp.async.commit_group;"); }
DEV_INLINE void cp_wait0()  { asm volatile("cp.async.wait_group 0;" ::: "memory"); }
DEV_INLINE void cp_wait1()  { asm volatile("cp.async.wait_group 1;" ::: "memory"); }

DEV_INLINE unsigned packh2(float lo, float hi) {
    unsigned r; asm("cvt.rn.f16x2.f32 %0, %1, %2;" : "=r"(r) : "f"(hi), "f"(lo));
    return r;
}

DEV_INLINE void mma16(float* c, const unsigned* a, unsigned b0, unsigned b1) {
    asm("mma.sync.aligned.m16n8k16.row.col.f32.f16.f16.f32 "
        "{%0,%1,%2,%3}, {%4,%5,%6,%7}, {%8,%9}, {%0,%1,%2,%3};"
        : "+f"(c[0]), "+f"(c[1]), "+f"(c[2]), "+f"(c[3])
        : "r"(a[0]), "r"(a[1]), "r"(a[2]), "r"(a[3]), "r"(b0), "r"(b1));
}

DEV_INLINE void msplit(float v, float& hf, float& lf) {
    const unsigned h = __float_as_uint(v) & H_MASK;
    hf = __uint_as_float(h);
    lf = v - hf;
}

// ---- prep: composite pair products x64 -> f16 hi/lo, B-frag-native ----
// (layout verified R10/R12/R13)
__global__ void prep_pairs(const float* __restrict__ cores_mid) {
    __shared__ float sW0[2048], sW1[2048];
    const int p = blockIdx.x;
    const float* s0 = cores_mid + (size_t)(2 * p) * 2048;
    const float* s1 = cores_mid + (size_t)(2 * p + 1) * 2048;
    for (int i = threadIdx.x; i < 2048; i += blockDim.x) { sW0[i] = s0[i]; sW1[i] = s1[i]; }
    __syncthreads();

    unsigned* dst = g_Bt + (size_t)p * 4096;
    for (int i = threadIdx.x; i < 4096; i += blockDim.x) {
        const int s = i & 3, lane = (i >> 2) & 31, tj = i >> 7;
        const int T = tj >> 2, j = tj & 3;
        const int q = lane & 3, g = lane >> 2;
        const int reg = s & 1, term = s >> 1;
        const int k0 = 16 * T + 2 * q + 8 * reg;
        const int n  = 8 * j + g;

        float v[2];
        #pragma unroll
        for (int e = 0; e < 2; e++) {
            const int k = k0 + e, ci = k >> 5, a = k & 31;
            const float* r0 = sW0 + (ci & 1) * 1024 + a * 32;
            const float* r1 = sW1 + (ci >> 1) * 1024 + n;
            float acc = 0.f;
            #pragma unroll 8
            for (int cc = 0; cc < 32; cc++) acc += r0[cc] * r1[cc * 32];
            v[e] = acc * W_SCALE;
        }
        float h0, l0, h1, l1;
        msplit(v[0], h0, l0);
        msplit(v[1], h1, l1);
        dst[i] = (term == 0) ? packh2(h0, h1) : packh2(l0, l1);
    }
}

__global__ void __launch_bounds__(TPB, 4)
mps_hmma_kernel(const float* __restrict__ x,
                const float* __restrict__ core0,
                const float* __restrict__ coreN,
                float* __restrict__ out, int B)
{
    __shared__ __align__(16) unsigned sW[2][4096];   // 2 stages x 16KB

    const int tid  = threadIdx.x;
    const int lane = tid & 31;
    const int w    = tid >> 5;
    const int q    = lane & 3;
    const int g    = lane >> 2;
    const int rowbase = blockIdx.x * ROWS_PER_CTA + w * 16;

    int rows[2];
    rows[0] = min(rowbase + g,     B - 1);
    rows[1] = min(rowbase + g + 8, B - 1);

    // prefetch pair-0 tile (16KB)
    {
        const unsigned* gsrc = g_Bt;
        const unsigned sb = smem_u32(&sW[0][0]);
        #pragma unroll
        for (int i = 0; i < 8; i++) {
            const int idx = tid + i * TPB;
            cp16(sb + idx * 16, gsrc + idx * 4);
        }
        cp_commit();
    }

    // ---- init acc = M0 (c-frag layout), then normalize to NORM_TGT ----
    float acc[16];
    #pragma unroll
    for (int rs = 0; rs < 2; rs++) {
        float s0, c0;
        __sincosf(HALF_PI * __ldg(x + (size_t)rows[rs] * L), &s0, &c0);
        #pragma unroll
        for (int j = 0; j < 4; j++)
            #pragma unroll
            for (int pp = 0; pp < 2; pp++) {
                const int col = 8 * j + 2 * q + pp;
                acc[4 * j + 2 * rs + pp] = c0 * core0[col] + s0 * core0[32 + col];
            }
    }
    #pragma unroll
    for (int rs = 0; rs < 2; rs++) {
        float ss = 0.f;
        #pragma unroll
        for (int j = 0; j < 4; j++) {
            const float v0 = acc[4 * j + 2 * rs];
            const float v1 = acc[4 * j + 2 * rs + 1];
            ss += v0 * v0 + v1 * v1;
        }
        ss += __shfl_xor_sync(0xffffffffu, ss, 1);
        ss += __shfl_xor_sync(0xffffffffu, ss, 2);
        const float r = NORM_TGT * rsqrtf(ss);
        #pragma unroll
        for (int j = 0; j < 4; j++) {
            acc[4 * j + 2 * rs]     *= r;
            acc[4 * j + 2 * rs + 1] *= r;
        }
    }

    // pair-0 scalars
    float sc[4][2];
    #pragma unroll
    for (int rs = 0; rs < 2; rs++) {
        float s1v, c1v, s2v, c2v;
        __sincosf(HALF_PI * __ldg(x + (size_t)rows[rs] * L + 1), &s1v, &c1v);
        __sincosf(HALF_PI * __ldg(x + (size_t)rows[rs] * L + 2), &s2v, &c2v);
        sc[0][rs] = c1v * c2v;  sc[1][rs] = s1v * c2v;
        sc[2][rs] = c1v * s2v;  sc[3][rs] = s1v * s2v;
    }

    // Wait for pair-0 tile and ensure all warps see initialized smem once.
    cp_wait0();
    __syncthreads();

    // ---- 127 composite steps ----
    // Pipeline invariant at loop top of pair p: stage p is in flight or
    // arrived (issued at top of p-1, or pre-loop for p=0); buffer (p+1)&1
    // holds stage p-1, all of whose reads completed before the barrier at
    // the end of iteration p-1 -> safe to overwrite with no sync here.
    for (int p = 0; p < NPAIR; p++) {
        if (p + 1 < NPAIR) {
            const unsigned* gsrc = g_Bt + (size_t)(p + 1) * 4096;
            const unsigned sb = smem_u32(&sW[(p + 1) & 1][0]);
            #pragma unroll
            for (int i = 0; i < 8; i++) {
                const int idx = tid + i * TPB;
                cp16(sb + idx * 16, gsrc + idx * 4);
            }
            cp_commit();
            cp_wait1();       // stage p arrived; p+1 still in flight
        } else {
            cp_wait0();
        }

        const unsigned* W = &sW[p & 1][0];

        // split A ONCE (unscaled): a-frag tk packs acc[8tk..8tk+7] pairwise
        unsigned ahi[2][4], alo[2][4];
        #pragma unroll
        for (int tk = 0; tk < 2; tk++)
            #pragma unroll
            for (int i = 0; i < 4; i++) {
                float h0, l0, h1, l1;
                msplit(acc[8 * tk + 2 * i],     h0, l0);
                msplit(acc[8 * tk + 2 * i + 1], h1, l1);
                ahi[tk][i] = packh2(h0, h1);
                alo[tk][i] = packh2(l0, l1);
            }

        float nacc[16];
        float P0[16], P1[16];   // ci-parity banks

        #pragma unroll
        for (int ci = 0; ci < 4; ci++) {
            float* P = (ci & 1) ? P1 : P0;
            #pragma unroll
            for (int k = 0; k < 16; k++) P[k] = 0.f;

            #pragma unroll
            for (int tk = 0; tk < 2; tk++) {
                const int T = 2 * ci + tk;
                #pragma unroll
                for (int j = 0; j < 4; j++) {
                    const uint4 b = *reinterpret_cast<const uint4*>(
                        W + ((size_t)(T * 4 + j) * 32 + lane) * 4);
                    mma16(&P[4 * j], ahi[tk], b.x, b.y);   // hi*Bhi
                    mma16(&P[4 * j], ahi[tk], b.z, b.w);   // hi*Blo
                    mma16(&P[4 * j], alo[tk], b.x, b.y);   // lo*Bhi
                }
            }

            // fold this family: nacc (+)= sc[ci][rs] * P
            const float s0 = sc[ci][0], s1 = sc[ci][1];
            if (ci == 0) {
                #pragma unroll
                for (int j = 0; j < 4; j++) {
                    nacc[4 * j + 0] = s0 * P[4 * j + 0];
                    nacc[4 * j + 1] = s0 * P[4 * j + 1];
                    nacc[4 * j + 2] = s1 * P[4 * j + 2];
                    nacc[4 * j + 3] = s1 * P[4 * j + 3];
                }
            } else {
                #pragma unroll
                for (int j = 0; j < 4; j++) {
                    nacc[4 * j + 0] = fmaf(s0, P[4 * j + 0], nacc[4 * j + 0]);
                    nacc[4 * j + 1] = fmaf(s0, P[4 * j + 1], nacc[4 * j + 1]);
                    nacc[4 * j + 2] = fmaf(s1, P[4 * j + 2], nacc[4 * j + 2]);
                    nacc[4 * j + 3] = fmaf(s1, P[4 * j + 3], nacc[4 * j + 3]);
                }
            }
        }

        // All reads of stage p are done -> barrier HERE (tails below run
        // outside the barrier window and overlap other warps' next MMAs).
        __syncthreads();

        // next pair's scalars (x-only)
        if (p + 1 < NPAIR) {
            #pragma unroll
            for (int rs = 0; rs < 2; rs++) {
                float s1v, c1v, s2v, c2v;
                __sincosf(HALF_PI * __ldg(x + (size_t)rows[rs] * L + (2 * p + 3)), &s1v, &c1v);
                __sincosf(HALF_PI * __ldg(x + (size_t)rows[rs] * L + (2 * p + 4)), &s2v, &c2v);
                sc[0][rs] = c1v * c2v;  sc[1][rs] = s1v * c2v;
                sc[2][rs] = c1v * s2v;  sc[3][rs] = s1v * s2v;
            }
        }

        #pragma unroll
        for (int k = 0; k < 16; k++) acc[k] = nacc[k];

        // rescale to NORM_TGT every 2 pairs (absorbs x64 W scale; keeps
        // acc entries + lo-parts in f16 range for the next A-split)
        if (p & 1) {
            #pragma unroll
            for (int rs = 0; rs < 2; rs++) {
                float ss = 0.f;
                #pragma unroll
                for (int j = 0; j < 4; j++) {
                    const float v0 = acc[4 * j + 2 * rs];
                    const float v1 = acc[4 * j + 2 * rs + 1];
                    ss += v0 * v0 + v1 * v1;
                }
                ss += __shfl_xor_sync(0xffffffffu, ss, 1);
                ss += __shfl_xor_sync(0xffffffffu, ss, 2);
                const float r = NORM_TGT * rsqrtf(ss);
                #pragma unroll
                for (int j = 0; j < 4; j++) {
                    acc[4 * j + 2 * rs]     *= r;
                    acc[4 * j + 2 * rs + 1] *= r;
                }
            }
        }
    }

    // ---- readout: eps-free unit normalize + coreN contraction ----
    #pragma unroll
    for (int rs = 0; rs < 2; rs++) {
        const int row = rowbase + g + 8 * rs;

        float ss = 0.f;
        #pragma unroll
        for (int j = 0; j < 4; j++) {
            const float v0 = acc[4 * j + 2 * rs];
            const float v1 = acc[4 * j + 2 * rs + 1];
            ss += v0 * v0 + v1 * v1;
        }
        ss += __shfl_xor_sync(0xffffffffu, ss, 1);
        ss += __shfl_xor_sync(0xffffffffu, ss, 2);
        const float inv = rsqrtf(ss);           // NO eps (R1 lesson)

        float sL, cL;
        __sincosf(HALF_PI * __ldg(x + (size_t)rows[rs] * L + (L - 1)), &sL, &cL);

        float lg[C];
        #pragma unroll
        for (int cc = 0; cc < C; cc++) lg[cc] = 0.f;
        #pragma unroll
        for (int j = 0; j < 4; j++)
            #pragma unroll
            for (int pp = 0; pp < 2; pp++) {
                const int col = 8 * j + 2 * q + pp;
                const float m = acc[4 * j + 2 * rs + pp];
                #pragma unroll
                for (int cc = 0; cc < C; cc++) {
                    const float wv = cL * coreN[col * C + cc]
                                   + sL * coreN[D * C + col * C + cc];
                    lg[cc] += m * wv;
                }
            }
        #pragma unroll
        for (int cc = 0; cc < C; cc++) {
            lg[cc] += __shfl_xor_sync(0xffffffffu, lg[cc], 1);
            lg[cc] += __shfl_xor_sync(0xffffffffu, lg[cc], 2);
        }
        if (q == 0 && row < B) {
            #pragma unroll
            for (int cc = 0; cc < C; cc++)
                out[(size_t)row * C + cc] = lg[cc] * inv;
        }
    }
}

extern "C" void kernel_launch(void* const* d_in, const int* in_sizes, int n_in,
                              void* d_out, int out_size)
{
    const float* x         = (const float*)d_in[0];
    const float* core0     = (const float*)d_in[1];
    const float* cores_mid = (const float*)d_in[2];
    const float* coreN     = (const float*)d_in[3];
    float* out = (float*)d_out;

    const int B = in_sizes[0] / L;
    const int grid = (B + ROWS_PER_CTA - 1) / ROWS_PER_CTA;   // 512 for B=32768

    prep_pairs<<<NPAIR, 256>>>(cores_mid);
    mps_hmma_kernel<<<grid, TPB>>>(x, core0, coreN, out, B);
}